// round 6
// baseline (speedup 1.0000x reference)
#include <cuda_runtime.h>
#include <cuda_bf16.h>
#include <math.h>
#include <stdint.h>

// LSTM T=512, B=64, I=H=512 on GB300 (sm_103a via compute_103, HMMA path).
// Kernel 1: split W fp32 -> bf16 hi/lo, transposed to [n][k] (one-time).
// Kernel 2: gx2[kh][t][col][b] = x_t @ Wx(kh-half) (+bias on kh=0). 512 CTAs (per t).
// Kernel 3: persistent loop, 128 CTAs = 64 cluster-pairs x 2 K-halves of h.
//   Per step: stage h-half -> GEMM(64x32x256, 3-pass bf16 split) ->
//   kgh1 pushes partial to peer SMEM (st.shared::cluster) -> cluster barrier ->
//   kgh0 local elementwise (gates = part0+part1+gx0+gx1) -> ONE grid barrier.

#define T_STEPS 512
#define B_SZ    64
#define H_SZ    512
#define G4      2048
#define NCTA    128
#define NTHR    256

// ---------------- global scratch ----------------
__device__ __align__(16) __nv_bfloat16 g_w_hi[(size_t)G4 * 1024];  // [n][k]
__device__ __align__(16) __nv_bfloat16 g_w_lo[(size_t)G4 * 1024];
__device__ float g_gx2[2][(size_t)T_STEPS * G4 * B_SZ];            // [kh][t][col][b]
__device__ __align__(16) __nv_bfloat16 g_h_hi[B_SZ * H_SZ];        // [b][j]
__device__ __align__(16) __nv_bfloat16 g_h_lo[B_SZ * H_SZ];
__device__ unsigned g_bar;

__device__ __forceinline__ float sigmoidf_fast(float x) {
    return 1.0f / (1.0f + __expf(-x));
}
__device__ __forceinline__ float tanhf_fast(float x) {
    return 2.0f / (1.0f + __expf(-2.0f * x)) - 1.0f;
}
__device__ __forceinline__ void mma_bf16(float* d, const uint32_t* a, const uint32_t* b) {
    asm volatile(
        "mma.sync.aligned.m16n8k16.row.col.f32.bf16.bf16.f32 "
        "{%0,%1,%2,%3}, {%4,%5,%6,%7}, {%8,%9}, {%0,%1,%2,%3};"
        : "+f"(d[0]), "+f"(d[1]), "+f"(d[2]), "+f"(d[3])
        : "r"(a[0]), "r"(a[1]), "r"(a[2]), "r"(a[3]), "r"(b[0]), "r"(b[1]));
}
__device__ __forceinline__ uint32_t smem_u32(const void* p) {
    uint32_t a;
    asm("{ .reg .u64 t; cvta.to.shared.u64 t, %1; cvt.u32.u64 %0, t; }" : "=r"(a) : "l"(p));
    return a;
}
__device__ __forceinline__ void grid_barrier(unsigned target) {
    __syncthreads();
    if (threadIdx.x == 0) {
        unsigned* bar = &g_bar;
        asm volatile("red.release.gpu.add.u32 [%0], 1;" :: "l"(bar) : "memory");
        unsigned v;
        do {
            asm volatile("ld.acquire.gpu.u32 %0, [%1];" : "=r"(v) : "l"(bar) : "memory");
        } while (v < target);
    }
    __syncthreads();
}

// ============================================================================
// Kernel 1: W split + transpose.  W[k][n] fp32 -> g_w_hi/lo[n][k] bf16.
// ============================================================================
extern "C" __global__ void __launch_bounds__(NTHR, 1)
lstm_wsplit_kernel(const float* __restrict__ W)
{
    int gid = blockIdx.x * NTHR + threadIdx.x;   // 262144 total
    int n  = gid >> 7;
    int k8 = (gid & 127) * 8;
    union { __nv_bfloat16 b[8]; uint4 v; } uh, ul;
    #pragma unroll
    for (int i = 0; i < 8; i++) {
        float w = W[(size_t)(k8 + i) * G4 + n];
        __nv_bfloat16 hi = __float2bfloat16_rn(w);
        uh.b[i] = hi;
        ul.b[i] = __float2bfloat16_rn(w - __bfloat162float(hi));
    }
    *(uint4*)(g_w_hi + (size_t)n * 1024 + k8) = uh.v;
    *(uint4*)(g_w_lo + (size_t)n * 1024 + k8) = ul.v;
}

// ============================================================================
// Kernel 2: gx. One CTA per t.  A = x_t (64 x 512) hi/lo in SMEM (stride 1040 B),
// W streamed per 32-col ntile from g_w. Warps: mg(2M) x nb(2N) x kh(2K-halves),
// warp tile M32 x N16 x K256. Each kh STGs its own g_gx2[kh] (no reduction).
// ============================================================================
#define GX_ASTR 1040
#define GX_AHI  0
#define GX_ALO  66560
#define GX_WHI  133120
#define GX_WLO  166400
#define GX_SMEM 199680

extern "C" __global__ void __launch_bounds__(NTHR, 1)
lstm_gx_kernel(const float* __restrict__ x, const float* __restrict__ bias)
{
    extern __shared__ char smem[];
    const int tid = threadIdx.x;
    const int t   = blockIdx.x;
    const int wid = tid >> 5;
    const int lid = tid & 31;
    const int grp = lid >> 2;
    const int tg  = lid & 3;
    const int mg  = wid & 1;
    const int nb  = (wid >> 1) & 1;
    const int kh  = wid >> 2;

    // stage x_t -> bf16 hi/lo smem [b][k]
    {
        const float4* x4 = (const float4*)(x + (size_t)t * B_SZ * 512);
        #pragma unroll
        for (int q = 0; q < 32; q++) {
            int idx = tid + q * NTHR;        // 8192 float4
            int r  = idx >> 7;
            int c4 = idx & 127;
            float4 v = x4[r * 128 + c4];
            __nv_bfloat16 h0 = __float2bfloat16_rn(v.x);
            __nv_bfloat16 h1 = __float2bfloat16_rn(v.y);
            __nv_bfloat16 h2 = __float2bfloat16_rn(v.z);
            __nv_bfloat16 h3 = __float2bfloat16_rn(v.w);
            int o = r * GX_ASTR + c4 * 8;
            *(__nv_bfloat162*)(smem + GX_AHI + o)     = __nv_bfloat162(h0, h1);
            *(__nv_bfloat162*)(smem + GX_AHI + o + 4) = __nv_bfloat162(h2, h3);
            *(__nv_bfloat162*)(smem + GX_ALO + o) =
                __nv_bfloat162(__float2bfloat16_rn(v.x - __bfloat162float(h0)),
                               __float2bfloat16_rn(v.y - __bfloat162float(h1)));
            *(__nv_bfloat162*)(smem + GX_ALO + o + 4) =
                __nv_bfloat162(__float2bfloat16_rn(v.z - __bfloat162float(h2)),
                               __float2bfloat16_rn(v.w - __bfloat162float(h3)));
        }
    }

    for (int ntile = 0; ntile < 64; ntile++) {
        __syncthreads();   // prior GEMM done before W overwrite (and x staged, 1st iter)
        // stage W chunk: cols [ntile*32,+32), k in [0,512): pure bf16 copies
        #pragma unroll
        for (int q = 0; q < 8; q++) {
            int idx = tid + q * NTHR;        // 2048 uint4 per array
            int n   = idx >> 6;
            int k16 = idx & 63;
            size_t src = (size_t)(ntile * 32 + n) * 1024 + k16 * 8;
            int o = n * GX_ASTR + k16 * 16;
            *(uint4*)(smem + GX_WHI + o) = *(const uint4*)(g_w_hi + src);
            *(uint4*)(smem + GX_WLO + o) = *(const uint4*)(g_w_lo + src);
        }
        __syncthreads();

        float acc[2][2][4];
        #pragma unroll
        for (int mi = 0; mi < 2; mi++)
            #pragma unroll
            for (int ni = 0; ni < 2; ni++) {
                acc[mi][ni][0]=0.f; acc[mi][ni][1]=0.f; acc[mi][ni][2]=0.f; acc[mi][ni][3]=0.f;
            }

        #pragma unroll 4
        for (int ks = 0; ks < 16; ks++) {
            const int kb = kh * 512 + ks * 32;   // byte offset within row
            uint32_t a_hi[8], a_lo[8];
            #pragma unroll
            for (int mi = 0; mi < 2; mi++) {
                const char* arow = smem + (mg * 32 + mi * 16 + grp) * GX_ASTR + tg * 4 + kb;
                a_hi[mi*4+0] = *(const uint32_t*)(arow + GX_AHI);
                a_hi[mi*4+1] = *(const uint32_t*)(arow + GX_AHI + 8 * GX_ASTR);
                a_hi[mi*4+2] = *(const uint32_t*)(arow + GX_AHI + 16);
                a_hi[mi*4+3] = *(const uint32_t*)(arow + GX_AHI + 8 * GX_ASTR + 16);
                a_lo[mi*4+0] = *(const uint32_t*)(arow + GX_ALO);
                a_lo[mi*4+1] = *(const uint32_t*)(arow + GX_ALO + 8 * GX_ASTR);
                a_lo[mi*4+2] = *(const uint32_t*)(arow + GX_ALO + 16);
                a_lo[mi*4+3] = *(const uint32_t*)(arow + GX_ALO + 8 * GX_ASTR + 16);
            }
            #pragma unroll
            for (int ni = 0; ni < 2; ni++) {
                const char* brow = smem + (nb * 16 + ni * 8 + grp) * GX_ASTR + tg * 4 + kb;
                uint32_t b_hi[2], b_lo[2];
                b_hi[0] = *(const uint32_t*)(brow + GX_WHI);
                b_hi[1] = *(const uint32_t*)(brow + GX_WHI + 16);
                b_lo[0] = *(const uint32_t*)(brow + GX_WLO);
                b_lo[1] = *(const uint32_t*)(brow + GX_WLO + 16);
                #pragma unroll
                for (int mi = 0; mi < 2; mi++) {
                    mma_bf16(acc[mi][ni], &a_hi[mi*4], b_hi);
                    mma_bf16(acc[mi][ni], &a_hi[mi*4], b_lo);
                    mma_bf16(acc[mi][ni], &a_lo[mi*4], b_hi);
                }
            }
        }
        // epilogue: STG to g_gx2[kh]; bias folded into kh==0 half
        #pragma unroll
        for (int mi = 0; mi < 2; mi++) {
            #pragma unroll
            for (int ni = 0; ni < 2; ni++) {
                int col = ntile * 32 + nb * 16 + ni * 8 + tg * 2;
                int b0  = mg * 32 + mi * 16 + grp;
                float bi0 = 0.f, bi1 = 0.f;
                if (kh == 0) { bi0 = bias[col]; bi1 = bias[col + 1]; }
                float* dst = g_gx2[kh] + ((size_t)t * G4 + col) * B_SZ;
                dst[b0]             = acc[mi][ni][0] + bi0;
                dst[B_SZ + b0]      = acc[mi][ni][1] + bi1;
                dst[b0 + 8]         = acc[mi][ni][2] + bi0;
                dst[B_SZ + b0 + 8]  = acc[mi][ni][3] + bi1;
            }
        }
    }
}

// ============================================================================
// Kernel 3: persistent recurrent loop (clusters of 2).
//  bid = p*2 + kgh.  Pair p owns gate cols {g*512 + p*8 + j : g<4, j<8} (n'=g*8+j)
//  and h cols [p*8, p*8+8).  kgh = K-half of h (k in [kgh*256,+256)).
// ============================================================================
#define LP_ASTR 528
#define LP_AHI  0
#define LP_ALO  33792
#define LP_WHI  67584
#define LP_WLO  84480
#define LP_GPL  101376                 // local partial  [32 n][68 pad] fp32
#define LP_GPR  110080                 // remote partial (peer writes here)
#define LP_SMEM 118784

extern "C" __global__ void __launch_bounds__(NTHR, 1) __cluster_dims__(2, 1, 1)
lstm_loop_kernel(const float* __restrict__ hidden0,
                 const float* __restrict__ cell0,
                 float* __restrict__ out)
{
    extern __shared__ char smem[];
    const uint32_t sbase = smem_u32(smem);
    const int tid = threadIdx.x;
    const int bid = blockIdx.x;
    const int p   = bid >> 1;
    const int kgh = bid & 1;
    const int wid = tid >> 5;
    const int lid = tid & 31;
    const int grp = lid >> 2;
    const int tg  = lid & 3;
    const int mg  = wid & 3;          // 4 M-groups of 16
    const int nb  = wid >> 2;         // 2 N-groups of 16

    // ---- init: Wh slice -> SMEM [n'][k'] ----
    #pragma unroll
    for (int q = 0; q < 4; q++) {
        int idx = tid + q * NTHR;     // 1024 = 32 rows x 32 uint4
        int n   = idx >> 5;
        int k16 = idx & 31;
        int col = (n >> 3) * 512 + p * 8 + (n & 7);
        size_t src = (size_t)col * 1024 + 512 + kgh * 256 + k16 * 8;
        int o = n * LP_ASTR + k16 * 16;
        *(uint4*)(smem + LP_WHI + o) = *(const uint4*)(g_w_hi + src);
        *(uint4*)(smem + LP_WLO + o) = *(const uint4*)(g_w_lo + src);
    }

    // ---- state init (kgh0 owns elementwise; 2 elems per thread) ----
    float cs[2] = {0.f, 0.f};
    float hl[2] = {0.f, 0.f};
    if (kgh == 0) {
        #pragma unroll
        for (int i = 0; i < 2; i++) {
            int e  = tid + i * NTHR;
            int b  = e >> 3;
            int jj = e & 7;
            int col = p * 8 + jj;
            cs[i] = cell0[b * H_SZ + col];
            float hv = hidden0[b * H_SZ + col];
            __nv_bfloat16 hh = __float2bfloat16_rn(hv);
            g_h_hi[b * H_SZ + col] = hh;
            g_h_lo[b * H_SZ + col] = __float2bfloat16_rn(hv - __bfloat162float(hh));
        }
    }
    // prefetch gx(t=0)
    float gxp[2][4];
    if (kgh == 0) {
        #pragma unroll
        for (int i = 0; i < 2; i++) {
            int e = tid + i * NTHR;
            int b = e >> 3;
            int jj = e & 7;
            #pragma unroll
            for (int g = 0; g < 4; g++) {
                size_t a = ((size_t)g * 512 + p * 8 + jj) * B_SZ + b;
                gxp[i][g] = g_gx2[0][a] + g_gx2[1][a];
            }
        }
    }

    unsigned bar_n = 1;
    grid_barrier(NCTA * bar_n); bar_n++;

    for (int t = 0; t < T_STEPS; t++) {
        // ---- stage A: h[b][kgh*256 .. +256) hi/lo ----
        #pragma unroll
        for (int q = 0; q < 8; q++) {
            int idx = tid + q * NTHR;    // 2048 uint4 per array
            int r   = idx >> 5;
            int k16 = idx & 31;
            size_t src = (size_t)r * 512 + kgh * 256 + k16 * 8;
            int o = r * LP_ASTR + k16 * 16;
            *(uint4*)(smem + LP_AHI + o) = *(const uint4*)(g_h_hi + src);
            *(uint4*)(smem + LP_ALO + o) = *(const uint4*)(g_h_lo + src);
        }
        __syncthreads();

        // ---- GEMM 64x32x256, 3-pass, warp tile M16xN16 ----
        float acc[2][4];
        acc[0][0]=0.f; acc[0][1]=0.f; acc[0][2]=0.f; acc[0][3]=0.f;
        acc[1][0]=0.f; acc[1][1]=0.f; acc[1][2]=0.f; acc[1][3]=0.f;
        {
            const char* arow = smem + (mg * 16 + grp) * LP_ASTR + tg * 4;
            #pragma unroll 4
            for (int ks = 0; ks < 16; ks++) {
                const int kb = ks * 32;
                uint32_t a_hi[4], a_lo[4];
                a_hi[0] = *(const uint32_t*)(arow + LP_AHI + kb);
                a_hi[1] = *(const uint32_t*)(arow + LP_AHI + 8 * LP_ASTR + kb);
                a_hi[2] = *(const uint32_t*)(arow + LP_AHI + kb + 16);
                a_hi[3] = *(const uint32_t*)(arow + LP_AHI + 8 * LP_ASTR + kb + 16);
                a_lo[0] = *(const uint32_t*)(arow + LP_ALO + kb);
                a_lo[1] = *(const uint32_t*)(arow + LP_ALO + 8 * LP_ASTR + kb);
                a_lo[2] = *(const uint32_t*)(arow + LP_ALO + kb + 16);
                a_lo[3] = *(const uint32_t*)(arow + LP_ALO + 8 * LP_ASTR + kb + 16);
                #pragma unroll
                for (int nt = 0; nt < 2; nt++) {
                    const char* brow = smem + (nb * 16 + nt * 8 + grp) * LP_ASTR + tg * 4 + kb;
                    uint32_t b_hi[2], b_lo[2];
                    b_hi[0] = *(const uint32_t*)(brow + LP_WHI);
                    b_hi[1] = *(const uint32_t*)(brow + LP_WHI + 16);
                    b_lo[0] = *(const uint32_t*)(brow + LP_WLO);
                    b_lo[1] = *(const uint32_t*)(brow + LP_WLO + 16);
                    mma_bf16(acc[nt], a_hi, b_hi);
                    mma_bf16(acc[nt], a_hi, b_lo);
                    mma_bf16(acc[nt], a_lo, b_hi);
                }
            }
        }

        // ---- export partials ----
        if (kgh == 1) {
            // push straight from accumulators into peer (rank 0) GPR buffer
            #pragma unroll
            for (int nt = 0; nt < 2; nt++) {
                int n  = nb * 16 + nt * 8 + tg * 2;
                int b0 = mg * 16 + grp;
                uint32_t la0 = sbase + LP_GPR + (uint32_t)(n * 68 + b0) * 4;
                uint32_t la1 = la0 + 68 * 4;
                uint32_t r0, r1;
                asm("mapa.shared::cluster.u32 %0, %1, %2;" : "=r"(r0) : "r"(la0), "r"(0));
                asm("mapa.shared::cluster.u32 %0, %1, %2;" : "=r"(r1) : "r"(la1), "r"(0));
                asm volatile("st.shared::cluster.f32 [%0], %1;" :: "r"(r0), "f"(acc[nt][0]) : "memory");
                asm volatile("st.shared::cluster.f32 [%0], %1;" :: "r"(r1), "f"(acc[nt][1]) : "memory");
                asm volatile("st.shared::cluster.f32 [%0], %1;" :: "r"(r0 + 32), "f"(acc[nt][2]) : "memory");
                asm volatile("st.shared::cluster.f32 [%0], %1;" :: "r"(r1 + 32), "f"(acc[nt][3]) : "memory");
            }
        } else {
            float* gp = (float*)(smem + LP_GPL);
            #pragma unroll
            for (int nt = 0; nt < 2; nt++) {
                int n  = nb * 16 + nt * 8 + tg * 2;
                int b0 = mg * 16 + grp;
                gp[n * 68 + b0]           = acc[nt][0];
                gp[(n + 1) * 68 + b0]     = acc[nt][1];
                gp[n * 68 + b0 + 8]       = acc[nt][2];
                gp[(n + 1) * 68 + b0 + 8] = acc[nt][3];
            }
        }
        asm volatile("barrier.cluster.arrive.aligned;" ::: "memory");
        asm volatile("barrier.cluster.wait.aligned;" ::: "memory");
        __syncthreads();

        // ---- elementwise (kgh0 only) ----
        if (kgh == 0) {
            const float* gl = (const float*)(smem + LP_GPL);
            const float* gr = (const float*)(smem + LP_GPR);
            int tn = (t + 1 < T_STEPS) ? t + 1 : t;
            #pragma unroll
            for (int i = 0; i < 2; i++) {
                int e  = tid + i * NTHR;
                int b  = e >> 3;
                int jj = e & 7;
                float gate[4];
                #pragma unroll
                for (int g = 0; g < 4; g++) {
                    int n = g * 8 + jj;
                    gate[g] = gl[n * 68 + b] + gr[n * 68 + b] + gxp[i][g];
                }
                float f  = sigmoidf_fast(gate[0]);
                float ii = sigmoidf_fast(gate[1]);
                float cd = tanhf_fast(gate[2]);
                float o  = sigmoidf_fast(gate[3]);
                cs[i] = f * cs[i] + ii * cd;
                float h = o * tanhf_fast(cs[i]);
                hl[i] = h;
                int col = p * 8 + jj;
                out[(size_t)t * (B_SZ * H_SZ) + b * H_SZ + col] = h;
                __nv_bfloat16 hh = __float2bfloat16_rn(h);
                g_h_hi[b * H_SZ + col] = hh;
                g_h_lo[b * H_SZ + col] = __float2bfloat16_rn(h - __bfloat162float(hh));
                // prefetch gx for t+1
                #pragma unroll
                for (int g = 0; g < 4; g++) {
                    size_t a = ((size_t)tn * G4 + g * 512 + col) * B_SZ + b;
                    gxp[i][g] = g_gx2[0][a] + g_gx2[1][a];
                }
            }
        }

        grid_barrier(NCTA * bar_n); bar_n++;
    }

    // ---- final states ----
    if (kgh == 0) {
        size_t base = (size_t)T_STEPS * B_SZ * H_SZ;
        #pragma unroll
        for (int i = 0; i < 2; i++) {
            int e  = tid + i * NTHR;
            int b  = e >> 3;
            int jj = e & 7;
            int col = p * 8 + jj;
            out[base + b * H_SZ + col] = hl[i];
            out[base + B_SZ * H_SZ + b * H_SZ + col] = cs[i];
        }
    }
}

// ============================================================================
extern "C" void kernel_launch(void* const* d_in, const int* in_sizes, int n_in,
                              void* d_out, int out_size)
{
    (void)in_sizes; (void)n_in; (void)out_size;
    const float* x       = (const float*)d_in[0];
    const float* hidden0 = (const float*)d_in[1];
    const float* cell0   = (const float*)d_in[2];
    const float* W       = (const float*)d_in[3];
    const float* bias    = (const float*)d_in[4];
    float* out = (float*)d_out;

    void* bar_addr = nullptr;
    cudaGetSymbolAddress(&bar_addr, g_bar);
    cudaMemsetAsync(bar_addr, 0, sizeof(unsigned));

    cudaFuncSetAttribute(lstm_gx_kernel,
                         cudaFuncAttributeMaxDynamicSharedMemorySize, GX_SMEM);
    cudaFuncSetAttribute(lstm_loop_kernel,
                         cudaFuncAttributeMaxDynamicSharedMemorySize, LP_SMEM);

    lstm_wsplit_kernel<<<1024, NTHR>>>(W);
    lstm_gx_kernel<<<T_STEPS, NTHR, GX_SMEM>>>(x, bias);
    lstm_loop_kernel<<<NCTA, NTHR, LP_SMEM>>>(hidden0, cell0, out);
}

// round 7
// speedup vs baseline: 1.2497x; 1.2497x over previous
#include <cuda_runtime.h>
#include <cuda_bf16.h>
#include <math.h>
#include <stdint.h>

// LSTM T=512, B=64, I=H=512 on GB300 (sm_103a via compute_103, HMMA path).
// Persistent 128-CTA x 256-thread cooperative kernel, 2 grid barriers/step.
// CTA = cg*4+kg: cg in [0,32) owns 64 gate cols, kg in [0,4) owns 256 of K=1024.
// Per step: partial gates = A(64x256) @ W(256x64) via mma.sync m16n8k16 bf16,
// 3-pass split (A_hi*W_hi + A_hi*W_lo + A_lo*W_hi, fp32 accum).
// Round 7 changes vs round-3 baseline (3439us):
//  - flag-tree grid barrier (per-CTA padded flags + CTA0 aggregator + epoch bcast)
//  - cp.async (LDGSTS) staging of the A tile instead of LDG->STS

#define T_STEPS 512
#define B_SZ    64
#define H_SZ    512
#define I_SZ    512
#define G4      2048
#define NCTA    128
#define NTHR    256
#define KG_SZ   256
#define CG_COLS 64

// SMEM: padded bf16 tiles, row stride 264 elems (528B) -> conflict-free frag loads
#define ROW_STRIDE_B 528
#define TILE_BYTES   (64 * ROW_STRIDE_B)   // 33792
#define SM_BIAS 0
#define SM_A_HI 64
#define SM_A_LO (SM_A_HI + TILE_BYTES)
#define SM_W_HI (SM_A_LO + TILE_BYTES)
#define SM_W_LO (SM_W_HI + TILE_BYTES)
#define SM_TOTAL (SM_W_LO + TILE_BYTES)    // 135232

#define FLAG_STRIDE 32                      // 128B apart

__device__ __align__(16) __nv_bfloat16 g_x_hi[T_STEPS * B_SZ * I_SZ];
__device__ __align__(16) __nv_bfloat16 g_x_lo[T_STEPS * B_SZ * I_SZ];
__device__ __align__(16) __nv_bfloat16 g_h_hi[B_SZ * H_SZ];
__device__ __align__(16) __nv_bfloat16 g_h_lo[B_SZ * H_SZ];
__device__ float    g_part[4 * G4 * B_SZ];   // [kg][col][b]
__device__ unsigned g_flags[NCTA * FLAG_STRIDE];
__device__ unsigned g_epoch;

__device__ __forceinline__ float sigmoidf_fast(float x) {
    return 1.0f / (1.0f + __expf(-x));
}
__device__ __forceinline__ float tanhf_fast(float x) {
    return 2.0f / (1.0f + __expf(-2.0f * x)) - 1.0f;
}
__device__ __forceinline__ void mma_bf16(float* d, const uint32_t* a, const uint32_t* b) {
    asm volatile(
        "mma.sync.aligned.m16n8k16.row.col.f32.bf16.bf16.f32 "
        "{%0,%1,%2,%3}, {%4,%5,%6,%7}, {%8,%9}, {%0,%1,%2,%3};"
        : "+f"(d[0]), "+f"(d[1]), "+f"(d[2]), "+f"(d[3])
        : "r"(a[0]), "r"(a[1]), "r"(a[2]), "r"(a[3]), "r"(b[0]), "r"(b[1]));
}
__device__ __forceinline__ uint32_t smem_u32(const void* p) {
    uint32_t a;
    asm("{ .reg .u64 t; cvta.to.shared.u64 t, %1; cvt.u32.u64 %0, t; }" : "=r"(a) : "l"(p));
    return a;
}
__device__ __forceinline__ void cp16(uint32_t smem_dst, const void* gsrc) {
    asm volatile("cp.async.cg.shared.global [%0], [%1], 16;" :: "r"(smem_dst), "l"(gsrc) : "memory");
}
__device__ __forceinline__ void cp_commit_wait() {
    asm volatile("cp.async.commit_group;" ::: "memory");
    asm volatile("cp.async.wait_group 0;" ::: "memory");
}

// Flag-tree grid barrier. Epoch is monotonic per launch; flags/epoch are
// memset to 0 by kernel_launch before the kernel starts (graph-capturable).
__device__ __forceinline__ void grid_barrier(unsigned e, int bid, int tid) {
    __syncthreads();
    if (bid == 0) {
        if (tid == 0) {
            asm volatile("st.release.gpu.u32 [%0], %1;"
                         :: "l"(&g_flags[0]), "r"(e) : "memory");
        }
        if (tid < NCTA) {
            unsigned v;
            const unsigned* f = &g_flags[tid * FLAG_STRIDE];
            do {
                asm volatile("ld.acquire.gpu.u32 %0, [%1];" : "=r"(v) : "l"(f) : "memory");
            } while (v < e);
        }
        __syncthreads();
        if (tid == 0) {
            asm volatile("st.release.gpu.u32 [%0], %1;"
                         :: "l"(&g_epoch), "r"(e) : "memory");
        }
    } else {
        if (tid == 0) {
            asm volatile("st.release.gpu.u32 [%0], %1;"
                         :: "l"(&g_flags[bid * FLAG_STRIDE]), "r"(e) : "memory");
            unsigned v;
            do {
                asm volatile("ld.acquire.gpu.u32 %0, [%1];" : "=r"(v) : "l"(&g_epoch) : "memory");
            } while (v < e);
        }
        __syncthreads();
    }
}

extern "C" __global__ void __launch_bounds__(NTHR, 1)
lstm_hmma_kernel(const float* __restrict__ x,
                 const float* __restrict__ hidden0,
                 const float* __restrict__ cell0,
                 const float* __restrict__ W,
                 const float* __restrict__ bias,
                 float* __restrict__ out)
{
    extern __shared__ char smem[];
    float* sbias = (float*)(smem + SM_BIAS);
    const uint32_t sbase = smem_u32(smem);

    const int tid = threadIdx.x;
    const int bid = blockIdx.x;
    const int cg  = bid >> 2;
    const int kg  = bid & 3;
    const int wid = tid >> 5;
    const int lid = tid & 31;
    const int grp = lid >> 2;     // groupID 0..7
    const int tg  = lid & 3;      // thread-in-group

    // warp tile: 4 warps along M (batch), 2 along N (cols)
    const int m_base = (wid >> 1) * 16;
    const int n_base = (wid & 1) * 32;

    // elementwise ownership
    const int eb  = tid >> 2;
    const int ejj = tid & 3;
    const int ej  = bid * 4 + ejj;

    // ---- init: W slice -> SMEM bf16 hi/lo, layout [n][k] padded ----
    {
        const float* wsrc = W + (size_t)(kg * KG_SZ) * G4 + cg * CG_COLS;
        for (int idx = tid; idx < KG_SZ * CG_COLS; idx += NTHR) {
            int n = idx & 63;          // coalesced along n
            int k = idx >> 6;
            float w = wsrc[(size_t)k * G4 + n];
            __nv_bfloat16 hi = __float2bfloat16_rn(w);
            __nv_bfloat16 lo = __float2bfloat16_rn(w - __bfloat162float(hi));
            int o = n * ROW_STRIDE_B + k * 2;
            *(__nv_bfloat16*)(smem + SM_W_HI + o) = hi;
            *(__nv_bfloat16*)(smem + SM_W_LO + o) = lo;
        }
    }
    if (tid < 16) {
        int gate = tid >> 2;
        int jj   = tid & 3;
        sbias[tid] = bias[gate * H_SZ + bid * 4 + jj];
    }
    // ---- pre-split x -> bf16 hi/lo (grid-strided) ----
    {
        const float4* x4 = (const float4*)x;
        const int n4 = T_STEPS * B_SZ * I_SZ / 4;
        for (int i = bid * NTHR + tid; i < n4; i += NCTA * NTHR) {
            float4 v = x4[i];
            __nv_bfloat16 h0 = __float2bfloat16_rn(v.x);
            __nv_bfloat16 h1 = __float2bfloat16_rn(v.y);
            __nv_bfloat16 h2 = __float2bfloat16_rn(v.z);
            __nv_bfloat16 h3 = __float2bfloat16_rn(v.w);
            __nv_bfloat162* dh = (__nv_bfloat162*)(g_x_hi + 4 * (size_t)i);
            dh[0] = __nv_bfloat162(h0, h1);
            dh[1] = __nv_bfloat162(h2, h3);
            __nv_bfloat162* dl = (__nv_bfloat162*)(g_x_lo + 4 * (size_t)i);
            dl[0] = __nv_bfloat162(__float2bfloat16_rn(v.x - __bfloat162float(h0)),
                                   __float2bfloat16_rn(v.y - __bfloat162float(h1)));
            dl[1] = __nv_bfloat162(__float2bfloat16_rn(v.z - __bfloat162float(h2)),
                                   __float2bfloat16_rn(v.w - __bfloat162float(h3)));
        }
    }
    // ---- state init ----
    float c_state = cell0[eb * H_SZ + ej];
    {
        float hv = hidden0[eb * H_SZ + ej];
        __nv_bfloat16 hh = __float2bfloat16_rn(hv);
        g_h_hi[eb * H_SZ + ej] = hh;
        g_h_lo[eb * H_SZ + ej] = __float2bfloat16_rn(hv - __bfloat162float(hh));
    }
    float h_last = 0.0f;

    unsigned ep = 1;
    grid_barrier(ep, bid, tid); ep++;

    // ---- time loop ----
    for (int t = 0; t < T_STEPS; t++) {
        // stage A hi/lo via cp.async: rows b=0..63, k slice [kg*256, +256)
        {
            const __nv_bfloat16* sh;
            const __nv_bfloat16* sl;
            if (kg < 2) {
                size_t off = (size_t)t * B_SZ * I_SZ + kg * KG_SZ;
                sh = g_x_hi + off;
                sl = g_x_lo + off;
            } else {
                sh = g_h_hi + (kg - 2) * KG_SZ;
                sl = g_h_lo + (kg - 2) * KG_SZ;
            }
            #pragma unroll
            for (int it = 0; it < 8; it++) {
                int idx = tid + it * NTHR;       // 0..2047
                int r   = idx >> 5;              // 0..63
                int c16 = idx & 31;              // 16B unit
                uint32_t o = (uint32_t)(r * ROW_STRIDE_B + c16 * 16);
                cp16(sbase + SM_A_HI + o, sh + (size_t)r * 512 + c16 * 8);
                cp16(sbase + SM_A_LO + o, sl + (size_t)r * 512 + c16 * 8);
            }
            cp_commit_wait();
        }
        __syncthreads();

        // ---- 64x64x256 GEMM: 3-pass bf16 split, m16n8k16 ----
        float acc[4][4];
        #pragma unroll
        for (int i = 0; i < 4; i++) {
            acc[i][0] = 0.f; acc[i][1] = 0.f; acc[i][2] = 0.f; acc[i][3] = 0.f;
        }
        {
            const char* arow = smem + (m_base + grp) * ROW_STRIDE_B + tg * 4;
            #pragma unroll 4
            for (int ks = 0; ks < 16; ks++) {
                const int kb = ks * 32;   // byte offset of k0 within row
                uint32_t a_hi[4], a_lo[4];
                a_hi[0] = *(const uint32_t*)(arow + SM_A_HI + kb);
                a_hi[1] = *(const uint32_t*)(arow + SM_A_HI + 8 * ROW_STRIDE_B + kb);
                a_hi[2] = *(const uint32_t*)(arow + SM_A_HI + kb + 16);
                a_hi[3] = *(const uint32_t*)(arow + SM_A_HI + 8 * ROW_STRIDE_B + kb + 16);
                a_lo[0] = *(const uint32_t*)(arow + SM_A_LO + kb);
                a_lo[1] = *(const uint32_t*)(arow + SM_A_LO + 8 * ROW_STRIDE_B + kb);
                a_lo[2] = *(const uint32_t*)(arow + SM_A_LO + kb + 16);
                a_lo[3] = *(const uint32_t*)(arow + SM_A_LO + 8 * ROW_STRIDE_B + kb + 16);
                #pragma unroll
                for (int nt = 0; nt < 4; nt++) {
                    const char* brow = smem + (n_base + nt * 8 + grp) * ROW_STRIDE_B + tg * 4 + kb;
                    uint32_t b_hi[2], b_lo[2];
                    b_hi[0] = *(const uint32_t*)(brow + SM_W_HI);
                    b_hi[1] = *(const uint32_t*)(brow + SM_W_HI + 16);
                    b_lo[0] = *(const uint32_t*)(brow + SM_W_LO);
                    b_lo[1] = *(const uint32_t*)(brow + SM_W_LO + 16);
                    mma_bf16(acc[nt], a_hi, b_hi);
                    mma_bf16(acc[nt], a_hi, b_lo);
                    mma_bf16(acc[nt], a_lo, b_hi);
                }
            }
        }
        // write partials: g_part[kg][col][b]
        {
            #pragma unroll
            for (int nt = 0; nt < 4; nt++) {
                int col = cg * CG_COLS + n_base + nt * 8 + tg * 2;
                int b0  = m_base + grp;
                g_part[((size_t)kg * G4 + col)     * B_SZ + b0]     = acc[nt][0];
                g_part[((size_t)kg * G4 + col + 1) * B_SZ + b0]     = acc[nt][1];
                g_part[((size_t)kg * G4 + col)     * B_SZ + b0 + 8] = acc[nt][2];
                g_part[((size_t)kg * G4 + col + 1) * B_SZ + b0 + 8] = acc[nt][3];
            }
        }

        grid_barrier(ep, bid, tid); ep++;

        // elementwise: reduce 4 partials + bias, LSTM cell, emit h
        {
            float g0 = sbias[0 * 4 + ejj];
            float g1 = sbias[1 * 4 + ejj];
            float g2 = sbias[2 * 4 + ejj];
            float g3 = sbias[3 * 4 + ejj];
            #pragma unroll
            for (int kk = 0; kk < 4; kk++) {
                g0 += g_part[((size_t)kk * G4 + 0 * H_SZ + ej) * B_SZ + eb];
                g1 += g_part[((size_t)kk * G4 + 1 * H_SZ + ej) * B_SZ + eb];
                g2 += g_part[((size_t)kk * G4 + 2 * H_SZ + ej) * B_SZ + eb];
                g3 += g_part[((size_t)kk * G4 + 3 * H_SZ + ej) * B_SZ + eb];
            }
            float f  = sigmoidf_fast(g0);
            float ii = sigmoidf_fast(g1);
            float cd = tanhf_fast(g2);
            float o  = sigmoidf_fast(g3);
            c_state = f * c_state + ii * cd;
            float h = o * tanhf_fast(c_state);
            h_last = h;
            // h state first (critical path), then output
            __nv_bfloat16 hh = __float2bfloat16_rn(h);
            g_h_hi[eb * H_SZ + ej] = hh;
            g_h_lo[eb * H_SZ + ej] = __float2bfloat16_rn(h - __bfloat162float(hh));
            out[(size_t)t * (B_SZ * H_SZ) + eb * H_SZ + ej] = h;
        }

        grid_barrier(ep, bid, tid); ep++;
    }

    // final states
    {
        size_t base = (size_t)T_STEPS * B_SZ * H_SZ;
        out[base + eb * H_SZ + ej] = h_last;
        out[base + B_SZ * H_SZ + eb * H_SZ + ej] = c_state;
    }
}

extern "C" void kernel_launch(void* const* d_in, const int* in_sizes, int n_in,
                              void* d_out, int out_size)
{
    (void)in_sizes; (void)n_in; (void)out_size;
    const float* x       = (const float*)d_in[0];
    const float* hidden0 = (const float*)d_in[1];
    const float* cell0   = (const float*)d_in[2];
    const float* W       = (const float*)d_in[3];
    const float* bias    = (const float*)d_in[4];
    float* out = (float*)d_out;

    // reset barrier state each launch (graph-capturable async memsets)
    void* flags_addr = nullptr;
    void* epoch_addr = nullptr;
    cudaGetSymbolAddress(&flags_addr, g_flags);
    cudaGetSymbolAddress(&epoch_addr, g_epoch);
    cudaMemsetAsync(flags_addr, 0, sizeof(unsigned) * NCTA * FLAG_STRIDE);
    cudaMemsetAsync(epoch_addr, 0, sizeof(unsigned));

    cudaFuncSetAttribute(lstm_hmma_kernel,
                         cudaFuncAttributeMaxDynamicSharedMemorySize, SM_TOTAL);

    lstm_hmma_kernel<<<NCTA, NTHR, SM_TOTAL>>>(x, hidden0, cell0, W, bias, out);
}

// round 8
// speedup vs baseline: 1.5490x; 1.2395x over previous
#include <cuda_runtime.h>
#include <cuda_bf16.h>
#include <math.h>
#include <stdint.h>

// LSTM T=512, B=64, I=H=512 on GB300 (sm_103a via compute_103, HMMA path).
// Persistent 128-CTA x 256-thread cooperative kernel, 2 grid barriers/step.
// CTA = cg*4+kg: cg in [0,32) owns 64 gate cols, kg in [0,4) owns 256 of K=1024.
// Per step: partial gates = A(64x256) @ W(256x64) via mma.sync m16n8k16 bf16,
// 3-pass split (A_hi*W_hi + A_hi*W_lo + A_lo*W_hi, fp32 accum).
// Round 8 vs round-3 baseline (3439us):
//  - cp.async (LDGSTS) staging of A tiles   [kept from R7; L1 work measured lower]
//  - coalesced elementwise mapping (b fastest across lanes) for g_part gathers
//  - fast tanh (2 MUFU)
//  - barrier: R3's simple red.release + acquire-poll (flag-tree reverted)

#define T_STEPS 512
#define B_SZ    64
#define H_SZ    512
#define I_SZ    512
#define G4      2048
#define NCTA    128
#define NTHR    256
#define KG_SZ   256
#define CG_COLS 64

#define ROW_STRIDE_B 528
#define TILE_BYTES   (64 * ROW_STRIDE_B)   // 33792
#define SM_BIAS 0
#define SM_A_HI 64
#define SM_A_LO (SM_A_HI + TILE_BYTES)
#define SM_W_HI (SM_A_LO + TILE_BYTES)
#define SM_W_LO (SM_W_HI + TILE_BYTES)
#define SM_TOTAL (SM_W_LO + TILE_BYTES)    // 135232

__device__ __align__(16) __nv_bfloat16 g_x_hi[T_STEPS * B_SZ * I_SZ];
__device__ __align__(16) __nv_bfloat16 g_x_lo[T_STEPS * B_SZ * I_SZ];
__device__ __align__(16) __nv_bfloat16 g_h_hi[B_SZ * H_SZ];
__device__ __align__(16) __nv_bfloat16 g_h_lo[B_SZ * H_SZ];
__device__ float    g_part[4 * G4 * B_SZ];   // [kg][col][b]
__device__ unsigned g_bar;

__device__ __forceinline__ void grid_barrier(unsigned target) {
    __syncthreads();
    if (threadIdx.x == 0) {
        unsigned* bar = &g_bar;
        asm volatile("red.release.gpu.add.u32 [%0], 1;" :: "l"(bar) : "memory");
        unsigned v;
        do {
            asm volatile("ld.acquire.gpu.u32 %0, [%1];" : "=r"(v) : "l"(bar) : "memory");
        } while (v < target);
    }
    __syncthreads();
}

__device__ __forceinline__ float sigmoidf_fast(float x) {
    return 1.0f / (1.0f + __expf(-x));
}
__device__ __forceinline__ float tanhf_fast(float x) {
    return 2.0f / (1.0f + __expf(-2.0f * x)) - 1.0f;
}
__device__ __forceinline__ void mma_bf16(float* d, const uint32_t* a, const uint32_t* b) {
    asm volatile(
        "mma.sync.aligned.m16n8k16.row.col.f32.bf16.bf16.f32 "
        "{%0,%1,%2,%3}, {%4,%5,%6,%7}, {%8,%9}, {%0,%1,%2,%3};"
        : "+f"(d[0]), "+f"(d[1]), "+f"(d[2]), "+f"(d[3])
        : "r"(a[0]), "r"(a[1]), "r"(a[2]), "r"(a[3]), "r"(b[0]), "r"(b[1]));
}
__device__ __forceinline__ uint32_t smem_u32(const void* p) {
    uint32_t a;
    asm("{ .reg .u64 t; cvta.to.shared.u64 t, %1; cvt.u32.u64 %0, t; }" : "=r"(a) : "l"(p));
    return a;
}
__device__ __forceinline__ void cp16(uint32_t smem_dst, const void* gsrc) {
    asm volatile("cp.async.cg.shared.global [%0], [%1], 16;" :: "r"(smem_dst), "l"(gsrc) : "memory");
}
__device__ __forceinline__ void cp_commit_wait() {
    asm volatile("cp.async.commit_group;" ::: "memory");
    asm volatile("cp.async.wait_group 0;" ::: "memory");
}

extern "C" __global__ void __launch_bounds__(NTHR, 1)
lstm_hmma_kernel(const float* __restrict__ x,
                 const float* __restrict__ hidden0,
                 const float* __restrict__ cell0,
                 const float* __restrict__ W,
                 const float* __restrict__ bias,
                 float* __restrict__ out)
{
    extern __shared__ char smem[];
    float* sbias = (float*)(smem + SM_BIAS);
    const uint32_t sbase = smem_u32(smem);

    const int tid = threadIdx.x;
    const int bid = blockIdx.x;
    const int cg  = bid >> 2;
    const int kg  = bid & 3;
    const int wid = tid >> 5;
    const int lid = tid & 31;
    const int grp = lid >> 2;     // groupID 0..7
    const int tg  = lid & 3;      // thread-in-group

    // warp tile: 4 warps along M (batch), 2 along N (cols)
    const int m_base = (wid >> 1) * 16;
    const int n_base = (wid & 1) * 32;

    // elementwise ownership: b fastest across lanes -> coalesced g_part gathers
    const int jj = tid >> 6;      // 0..3
    const int b  = tid & 63;      // 0..63
    const int ej = bid * 4 + jj;  // global h column

    // ---- init: W slice -> SMEM bf16 hi/lo, layout [n][k] padded ----
    {
        const float* wsrc = W + (size_t)(kg * KG_SZ) * G4 + cg * CG_COLS;
        for (int idx = tid; idx < KG_SZ * CG_COLS; idx += NTHR) {
            int n = idx & 63;
            int k = idx >> 6;
            float w = wsrc[(size_t)k * G4 + n];
            __nv_bfloat16 hi = __float2bfloat16_rn(w);
            __nv_bfloat16 lo = __float2bfloat16_rn(w - __bfloat162float(hi));
            int o = n * ROW_STRIDE_B + k * 2;
            *(__nv_bfloat16*)(smem + SM_W_HI + o) = hi;
            *(__nv_bfloat16*)(smem + SM_W_LO + o) = lo;
        }
    }
    if (tid < 16) {
        int gate = tid >> 2;
        int j4   = tid & 3;
        sbias[tid] = bias[gate * H_SZ + bid * 4 + j4];
    }
    // ---- pre-split x -> bf16 hi/lo (grid-strided) ----
    {
        const float4* x4 = (const float4*)x;
        const int n4 = T_STEPS * B_SZ * I_SZ / 4;
        for (int i = bid * NTHR + tid; i < n4; i += NCTA * NTHR) {
            float4 v = x4[i];
            __nv_bfloat16 h0 = __float2bfloat16_rn(v.x);
            __nv_bfloat16 h1 = __float2bfloat16_rn(v.y);
            __nv_bfloat16 h2 = __float2bfloat16_rn(v.z);
            __nv_bfloat16 h3 = __float2bfloat16_rn(v.w);
            __nv_bfloat162* dh = (__nv_bfloat162*)(g_x_hi + 4 * (size_t)i);
            dh[0] = __nv_bfloat162(h0, h1);
            dh[1] = __nv_bfloat162(h2, h3);
            __nv_bfloat162* dl = (__nv_bfloat162*)(g_x_lo + 4 * (size_t)i);
            dl[0] = __nv_bfloat162(__float2bfloat16_rn(v.x - __bfloat162float(h0)),
                                   __float2bfloat16_rn(v.y - __bfloat162float(h1)));
            dl[1] = __nv_bfloat162(__float2bfloat16_rn(v.z - __bfloat162float(h2)),
                                   __float2bfloat16_rn(v.w - __bfloat162float(h3)));
        }
    }
    // ---- state init ----
    float c_state = cell0[b * H_SZ + ej];
    {
        float hv = hidden0[b * H_SZ + ej];
        __nv_bfloat16 hh = __float2bfloat16_rn(hv);
        g_h_hi[b * H_SZ + ej] = hh;
        g_h_lo[b * H_SZ + ej] = __float2bfloat16_rn(hv - __bfloat162float(hh));
    }
    float h_last = 0.0f;

    unsigned bar_n = 1;
    grid_barrier(NCTA * bar_n); bar_n++;

    // ---- time loop ----
    for (int t = 0; t < T_STEPS; t++) {
        // stage A hi/lo via cp.async: rows b'=0..63, k slice [kg*256, +256)
        {
            const __nv_bfloat16* sh;
            const __nv_bfloat16* sl;
            if (kg < 2) {
                size_t off = (size_t)t * B_SZ * I_SZ + kg * KG_SZ;
                sh = g_x_hi + off;
                sl = g_x_lo + off;
            } else {
                sh = g_h_hi + (kg - 2) * KG_SZ;
                sl = g_h_lo + (kg - 2) * KG_SZ;
            }
            #pragma unroll
            for (int it = 0; it < 8; it++) {
                int idx = tid + it * NTHR;       // 0..2047
                int r   = idx >> 5;              // 0..63
                int c16 = idx & 31;              // 16B unit
                uint32_t o = (uint32_t)(r * ROW_STRIDE_B + c16 * 16);
                cp16(sbase + SM_A_HI + o, sh + (size_t)r * 512 + c16 * 8);
                cp16(sbase + SM_A_LO + o, sl + (size_t)r * 512 + c16 * 8);
            }
            cp_commit_wait();
        }
        __syncthreads();

        // ---- 64x64x256 GEMM: 3-pass bf16 split, m16n8k16 ----
        float acc[4][4];
        #pragma unroll
        for (int i = 0; i < 4; i++) {
            acc[i][0] = 0.f; acc[i][1] = 0.f; acc[i][2] = 0.f; acc[i][3] = 0.f;
        }
        {
            const char* arow = smem + (m_base + grp) * ROW_STRIDE_B + tg * 4;
            #pragma unroll 4
            for (int ks = 0; ks < 16; ks++) {
                const int kb = ks * 32;
                uint32_t a_hi[4], a_lo[4];
                a_hi[0] = *(const uint32_t*)(arow + SM_A_HI + kb);
                a_hi[1] = *(const uint32_t*)(arow + SM_A_HI + 8 * ROW_STRIDE_B + kb);
                a_hi[2] = *(const uint32_t*)(arow + SM_A_HI + kb + 16);
                a_hi[3] = *(const uint32_t*)(arow + SM_A_HI + 8 * ROW_STRIDE_B + kb + 16);
                a_lo[0] = *(const uint32_t*)(arow + SM_A_LO + kb);
                a_lo[1] = *(const uint32_t*)(arow + SM_A_LO + 8 * ROW_STRIDE_B + kb);
                a_lo[2] = *(const uint32_t*)(arow + SM_A_LO + kb + 16);
                a_lo[3] = *(const uint32_t*)(arow + SM_A_LO + 8 * ROW_STRIDE_B + kb + 16);
                #pragma unroll
                for (int nt = 0; nt < 4; nt++) {
                    const char* brow = smem + (n_base + nt * 8 + grp) * ROW_STRIDE_B + tg * 4 + kb;
                    uint32_t b_hi[2], b_lo[2];
                    b_hi[0] = *(const uint32_t*)(brow + SM_W_HI);
                    b_hi[1] = *(const uint32_t*)(brow + SM_W_HI + 16);
                    b_lo[0] = *(const uint32_t*)(brow + SM_W_LO);
                    b_lo[1] = *(const uint32_t*)(brow + SM_W_LO + 16);
                    mma_bf16(acc[nt], a_hi, b_hi);
                    mma_bf16(acc[nt], a_hi, b_lo);
                    mma_bf16(acc[nt], a_lo, b_hi);
                }
            }
        }
        // write partials: g_part[kg][col][b]
        {
            #pragma unroll
            for (int nt = 0; nt < 4; nt++) {
                int col = cg * CG_COLS + n_base + nt * 8 + tg * 2;
                int b0  = m_base + grp;
                g_part[((size_t)kg * G4 + col)     * B_SZ + b0]     = acc[nt][0];
                g_part[((size_t)kg * G4 + col + 1) * B_SZ + b0]     = acc[nt][1];
                g_part[((size_t)kg * G4 + col)     * B_SZ + b0 + 8] = acc[nt][2];
                g_part[((size_t)kg * G4 + col + 1) * B_SZ + b0 + 8] = acc[nt][3];
            }
        }

        grid_barrier(NCTA * bar_n); bar_n++;

        // elementwise: coalesced reduce of 4 partials + bias, LSTM cell, emit h
        {
            float g0 = sbias[0 * 4 + jj];
            float g1 = sbias[1 * 4 + jj];
            float g2 = sbias[2 * 4 + jj];
            float g3 = sbias[3 * 4 + jj];
            #pragma unroll
            for (int kk = 0; kk < 4; kk++) {
                g0 += g_part[((size_t)kk * G4 + 0 * H_SZ + ej) * B_SZ + b];
                g1 += g_part[((size_t)kk * G4 + 1 * H_SZ + ej) * B_SZ + b];
                g2 += g_part[((size_t)kk * G4 + 2 * H_SZ + ej) * B_SZ + b];
                g3 += g_part[((size_t)kk * G4 + 3 * H_SZ + ej) * B_SZ + b];
            }
            float f  = sigmoidf_fast(g0);
            float ii = sigmoidf_fast(g1);
            float cd = tanhf_fast(g2);
            float o  = sigmoidf_fast(g3);
            c_state = f * c_state + ii * cd;
            float h = o * tanhf_fast(c_state);
            h_last = h;
            __nv_bfloat16 hh = __float2bfloat16_rn(h);
            g_h_hi[b * H_SZ + ej] = hh;
            g_h_lo[b * H_SZ + ej] = __float2bfloat16_rn(h - __bfloat162float(hh));
            out[(size_t)t * (B_SZ * H_SZ) + b * H_SZ + ej] = h;
        }

        grid_barrier(NCTA * bar_n); bar_n++;
    }

    // final states
    {
        size_t base = (size_t)T_STEPS * B_SZ * H_SZ;
        out[base + b * H_SZ + ej] = h_last;
        out[base + B_SZ * H_SZ + b * H_SZ + ej] = c_state;
    }
}

extern "C" void kernel_launch(void* const* d_in, const int* in_sizes, int n_in,
                              void* d_out, int out_size)
{
    (void)in_sizes; (void)n_in; (void)out_size;
    const float* x       = (const float*)d_in[0];
    const float* hidden0 = (const float*)d_in[1];
    const float* cell0   = (const float*)d_in[2];
    const float* W       = (const float*)d_in[3];
    const float* bias    = (const float*)d_in[4];
    float* out = (float*)d_out;

    void* bar_addr = nullptr;
    cudaGetSymbolAddress(&bar_addr, g_bar);
    cudaMemsetAsync(bar_addr, 0, sizeof(unsigned));

    cudaFuncSetAttribute(lstm_hmma_kernel,
                         cudaFuncAttributeMaxDynamicSharedMemorySize, SM_TOTAL);

    lstm_hmma_kernel<<<NCTA, NTHR, SM_TOTAL>>>(x, hidden0, cell0, W, bias, out);
}

// round 9
// speedup vs baseline: 1.7647x; 1.1392x over previous
#include <cuda_runtime.h>
#include <cuda_bf16.h>
#include <math.h>
#include <stdint.h>

// LSTM T=512, B=64, I=H=512 on GB300 (sm_103a via compute_103, HMMA path).
// EXACT round-3 baseline (best: 3439us) + two isolated changes:
//  1) grid barrier polls with nanosleep backoff (hot-L2-line contention fix)
//  2) fast tanh (2 MUFU) in the serial elementwise phase
// Everything else (staging, GEMM tiling, layouts, mappings) is byte-identical to R3.

#define T_STEPS 512
#define B_SZ    64
#define H_SZ    512
#define I_SZ    512
#define G4      2048
#define NCTA    128
#define NTHR    256
#define KG_SZ   256
#define CG_COLS 64

#define ROW_STRIDE_B 528
#define TILE_BYTES   (64 * ROW_STRIDE_B)   // 33792
#define SM_BIAS 0
#define SM_A_HI 64
#define SM_A_LO (SM_A_HI + TILE_BYTES)
#define SM_W_HI (SM_A_LO + TILE_BYTES)
#define SM_W_LO (SM_W_HI + TILE_BYTES)
#define SM_TOTAL (SM_W_LO + TILE_BYTES)    // 135232

__device__ __align__(16) __nv_bfloat16 g_x_hi[T_STEPS * B_SZ * I_SZ];
__device__ __align__(16) __nv_bfloat16 g_x_lo[T_STEPS * B_SZ * I_SZ];
__device__ __align__(16) __nv_bfloat16 g_h_hi[B_SZ * H_SZ];
__device__ __align__(16) __nv_bfloat16 g_h_lo[B_SZ * H_SZ];
__device__ float    g_part[4 * G4 * B_SZ];   // [kg][col][b]
__device__ unsigned g_bar;

// Grid barrier: single release-add counter; pollers back off with nanosleep so
// the hot L2 line isn't saturated by acquire-loads while arrivals commit.
__device__ __forceinline__ void grid_barrier(unsigned target) {
    __syncthreads();
    if (threadIdx.x == 0) {
        unsigned* bar = &g_bar;
        asm volatile("red.release.gpu.add.u32 [%0], 1;" :: "l"(bar) : "memory");
        unsigned v;
        asm volatile("ld.acquire.gpu.u32 %0, [%1];" : "=r"(v) : "l"(bar) : "memory");
        unsigned ns = 32;
        while (v < target) {
            __nanosleep(ns);
            if (ns < 256) ns <<= 1;
            asm volatile("ld.acquire.gpu.u32 %0, [%1];" : "=r"(v) : "l"(bar) : "memory");
        }
    }
    __syncthreads();
}

__device__ __forceinline__ float sigmoidf_fast(float x) {
    return 1.0f / (1.0f + __expf(-x));
}
__device__ __forceinline__ float tanhf_fast(float x) {
    return 2.0f / (1.0f + __expf(-2.0f * x)) - 1.0f;
}

__device__ __forceinline__ void mma_bf16(float* d, const uint32_t* a, const uint32_t* b) {
    asm volatile(
        "mma.sync.aligned.m16n8k16.row.col.f32.bf16.bf16.f32 "
        "{%0,%1,%2,%3}, {%4,%5,%6,%7}, {%8,%9}, {%0,%1,%2,%3};"
        : "+f"(d[0]), "+f"(d[1]), "+f"(d[2]), "+f"(d[3])
        : "r"(a[0]), "r"(a[1]), "r"(a[2]), "r"(a[3]), "r"(b[0]), "r"(b[1]));
}

extern "C" __global__ void __launch_bounds__(NTHR, 1)
lstm_hmma_kernel(const float* __restrict__ x,
                 const float* __restrict__ hidden0,
                 const float* __restrict__ cell0,
                 const float* __restrict__ W,
                 const float* __restrict__ bias,
                 float* __restrict__ out)
{
    extern __shared__ char smem[];
    float* sbias = (float*)(smem + SM_BIAS);

    const int tid = threadIdx.x;
    const int bid = blockIdx.x;
    const int cg  = bid >> 2;
    const int kg  = bid & 3;
    const int wid = tid >> 5;
    const int lid = tid & 31;
    const int grp = lid >> 2;     // groupID 0..7
    const int tg  = lid & 3;      // thread-in-group

    // warp tile: 4 warps along M (batch), 2 along N (cols)
    const int m_base = (wid >> 1) * 16;
    const int n_base = (wid & 1) * 32;

    // elementwise ownership (R3 mapping)
    const int eb  = tid >> 2;
    const int ejj = tid & 3;
    const int ej  = bid * 4 + ejj;

    // ---- init: W slice -> SMEM bf16 hi/lo, layout [n][k] padded ----
    {
        const float* wsrc = W + (size_t)(kg * KG_SZ) * G4 + cg * CG_COLS;
        for (int idx = tid; idx < KG_SZ * CG_COLS; idx += NTHR) {
            int n = idx & 63;          // coalesced along n
            int k = idx >> 6;
            float w = wsrc[(size_t)k * G4 + n];
            __nv_bfloat16 hi = __float2bfloat16_rn(w);
            __nv_bfloat16 lo = __float2bfloat16_rn(w - __bfloat162float(hi));
            int o = n * ROW_STRIDE_B + k * 2;
            *(__nv_bfloat16*)(smem + SM_W_HI + o) = hi;
            *(__nv_bfloat16*)(smem + SM_W_LO + o) = lo;
        }
    }
    if (tid < 16) {
        int gate = tid >> 2;
        int jj   = tid & 3;
        sbias[tid] = bias[gate * H_SZ + bid * 4 + jj];
    }
    // ---- pre-split x -> bf16 hi/lo (grid-strided) ----
    {
        const float4* x4 = (const float4*)x;
        const int n4 = T_STEPS * B_SZ * I_SZ / 4;
        for (int i = bid * NTHR + tid; i < n4; i += NCTA * NTHR) {
            float4 v = x4[i];
            __nv_bfloat16 h0 = __float2bfloat16_rn(v.x);
            __nv_bfloat16 h1 = __float2bfloat16_rn(v.y);
            __nv_bfloat16 h2 = __float2bfloat16_rn(v.z);
            __nv_bfloat16 h3 = __float2bfloat16_rn(v.w);
            __nv_bfloat162* dh = (__nv_bfloat162*)(g_x_hi + 4 * (size_t)i);
            dh[0] = __nv_bfloat162(h0, h1);
            dh[1] = __nv_bfloat162(h2, h3);
            __nv_bfloat162* dl = (__nv_bfloat162*)(g_x_lo + 4 * (size_t)i);
            dl[0] = __nv_bfloat162(__float2bfloat16_rn(v.x - __bfloat162float(h0)),
                                   __float2bfloat16_rn(v.y - __bfloat162float(h1)));
            dl[1] = __nv_bfloat162(__float2bfloat16_rn(v.z - __bfloat162float(h2)),
                                   __float2bfloat16_rn(v.w - __bfloat162float(h3)));
        }
    }
    // ---- state init ----
    float c_state = cell0[eb * H_SZ + ej];
    {
        float hv = hidden0[eb * H_SZ + ej];
        __nv_bfloat16 hh = __float2bfloat16_rn(hv);
        g_h_hi[eb * H_SZ + ej] = hh;
        g_h_lo[eb * H_SZ + ej] = __float2bfloat16_rn(hv - __bfloat162float(hh));
    }
    float h_last = 0.0f;

    unsigned bar_n = 1;
    grid_barrier(NCTA * bar_n); bar_n++;

    // ---- time loop ----
    for (int t = 0; t < T_STEPS; t++) {
        // stage A hi/lo: rows b=0..63, k slice [kg*256, +256), padded smem
        {
            const __nv_bfloat16* sh;
            const __nv_bfloat16* sl;
            if (kg < 2) {
                size_t off = (size_t)t * B_SZ * I_SZ + kg * KG_SZ;
                sh = g_x_hi + off;
                sl = g_x_lo + off;
            } else {
                sh = g_h_hi + (kg - 2) * KG_SZ;
                sl = g_h_lo + (kg - 2) * KG_SZ;
            }
            #pragma unroll
            for (int it = 0; it < 8; it++) {
                int idx = tid + it * NTHR;       // 0..2047
                int r   = idx >> 5;              // 0..63
                int c16 = idx & 31;              // 16B unit
                uint4 vh = *(const uint4*)(sh + (size_t)r * 512 + c16 * 8);
                uint4 vl = *(const uint4*)(sl + (size_t)r * 512 + c16 * 8);
                int o = r * ROW_STRIDE_B + c16 * 16;
                *(uint4*)(smem + SM_A_HI + o) = vh;
                *(uint4*)(smem + SM_A_LO + o) = vl;
            }
        }
        __syncthreads();

        // ---- 64x64x256 GEMM: 3-pass bf16 split, m16n8k16 ----
        float acc[4][4];
        #pragma unroll
        for (int i = 0; i < 4; i++) {
            acc[i][0] = 0.f; acc[i][1] = 0.f; acc[i][2] = 0.f; acc[i][3] = 0.f;
        }
        {
            const char* arow = smem + (m_base + grp) * ROW_STRIDE_B + tg * 4;
            #pragma unroll 4
            for (int ks = 0; ks < 16; ks++) {
                const int kb = ks * 32;   // byte offset of k0 within row
                uint32_t a_hi[4], a_lo[4];
                a_hi[0] = *(const uint32_t*)(arow + SM_A_HI + kb);
                a_hi[1] = *(const uint32_t*)(arow + SM_A_HI + 8 * ROW_STRIDE_B + kb);
                a_hi[2] = *(const uint32_t*)(arow + SM_A_HI + kb + 16);
                a_hi[3] = *(const uint32_t*)(arow + SM_A_HI + 8 * ROW_STRIDE_B + kb + 16);
                a_lo[0] = *(const uint32_t*)(arow + SM_A_LO + kb);
                a_lo[1] = *(const uint32_t*)(arow + SM_A_LO + 8 * ROW_STRIDE_B + kb);
                a_lo[2] = *(const uint32_t*)(arow + SM_A_LO + kb + 16);
                a_lo[3] = *(const uint32_t*)(arow + SM_A_LO + 8 * ROW_STRIDE_B + kb + 16);
                #pragma unroll
                for (int nt = 0; nt < 4; nt++) {
                    const char* brow = smem + (n_base + nt * 8 + grp) * ROW_STRIDE_B + tg * 4 + kb;
                    uint32_t b_hi[2], b_lo[2];
                    b_hi[0] = *(const uint32_t*)(brow + SM_W_HI);
                    b_hi[1] = *(const uint32_t*)(brow + SM_W_HI + 16);
                    b_lo[0] = *(const uint32_t*)(brow + SM_W_LO);
                    b_lo[1] = *(const uint32_t*)(brow + SM_W_LO + 16);
                    mma_bf16(acc[nt], a_hi, b_hi);
                    mma_bf16(acc[nt], a_hi, b_lo);
                    mma_bf16(acc[nt], a_lo, b_hi);
                }
            }
        }
        // write partials: g_part[kg][col][b]
        {
            #pragma unroll
            for (int nt = 0; nt < 4; nt++) {
                int col = cg * CG_COLS + n_base + nt * 8 + tg * 2;
                int b0  = m_base + grp;
                g_part[((size_t)kg * G4 + col)     * B_SZ + b0]     = acc[nt][0];
                g_part[((size_t)kg * G4 + col + 1) * B_SZ + b0]     = acc[nt][1];
                g_part[((size_t)kg * G4 + col)     * B_SZ + b0 + 8] = acc[nt][2];
                g_part[((size_t)kg * G4 + col + 1) * B_SZ + b0 + 8] = acc[nt][3];
            }
        }

        grid_barrier(NCTA * bar_n); bar_n++;

        // elementwise: reduce 4 partials + bias, apply LSTM cell
        {
            float g0 = sbias[0 * 4 + ejj];
            float g1 = sbias[1 * 4 + ejj];
            float g2 = sbias[2 * 4 + ejj];
            float g3 = sbias[3 * 4 + ejj];
            #pragma unroll
            for (int kk = 0; kk < 4; kk++) {
                g0 += g_part[((size_t)kk * G4 + 0 * H_SZ + ej) * B_SZ + eb];
                g1 += g_part[((size_t)kk * G4 + 1 * H_SZ + ej) * B_SZ + eb];
                g2 += g_part[((size_t)kk * G4 + 2 * H_SZ + ej) * B_SZ + eb];
                g3 += g_part[((size_t)kk * G4 + 3 * H_SZ + ej) * B_SZ + eb];
            }
            float f  = sigmoidf_fast(g0);
            float ii = sigmoidf_fast(g1);
            float cd = tanhf_fast(g2);
            float o  = sigmoidf_fast(g3);
            c_state = f * c_state + ii * cd;
            float h = o * tanhf_fast(c_state);
            h_last = h;
            __nv_bfloat16 hh = __float2bfloat16_rn(h);
            g_h_hi[eb * H_SZ + ej] = hh;
            g_h_lo[eb * H_SZ + ej] = __float2bfloat16_rn(h - __bfloat162float(hh));
            out[(size_t)t * (B_SZ * H_SZ) + eb * H_SZ + ej] = h;
        }

        grid_barrier(NCTA * bar_n); bar_n++;
    }

    // final states: out layout = output[T,B,H] ++ h_T[1,B,H] ++ c_T[1,B,H]
    {
        size_t base = (size_t)T_STEPS * B_SZ * H_SZ;
        out[base + eb * H_SZ + ej] = h_last;
        out[base + B_SZ * H_SZ + eb * H_SZ + ej] = c_state;
    }
}

extern "C" void kernel_launch(void* const* d_in, const int* in_sizes, int n_in,
                              void* d_out, int out_size)
{
    (void)in_sizes; (void)n_in; (void)out_size;
    const float* x       = (const float*)d_in[0];
    const float* hidden0 = (const float*)d_in[1];
    const float* cell0   = (const float*)d_in[2];
    const float* W       = (const float*)d_in[3];
    const float* bias    = (const float*)d_in[4];
    float* out = (float*)d_out;

    void* bar_addr = nullptr;
    cudaGetSymbolAddress(&bar_addr, g_bar);
    cudaMemsetAsync(bar_addr, 0, sizeof(unsigned));

    cudaFuncSetAttribute(lstm_hmma_kernel,
                         cudaFuncAttributeMaxDynamicSharedMemorySize, SM_TOTAL);

    lstm_hmma_kernel<<<NCTA, NTHR, SM_TOTAL>>>(x, hidden0, cell0, W, bias, out);
}